// round 5
// baseline (speedup 1.0000x reference)
#include <cuda_runtime.h>
#include <cuda_bf16.h>
#include <cstdint>

// ---------------------------------------------------------------------------
// Fused ConvTranspose3d(3->16,k3,s2,p1) * 0.5 -> AvgPool(2) -> +bias  reduces
// to a dense stride-1 VALID conv with a 2x2x2 kernel:
//   out[n,oc,z,y,w] = sum_ic sum_{a,b,c} x[n,ic,z+a,y+b,w+c]*fw[oc,ic,a,b,c] + fb[oc]
// x: (4,3,128,128,128) fp32, out: (4,16,127,127,127) fp32
// ---------------------------------------------------------------------------

#define IC 3
#define OC 16
#define DIN 128
#define DOUT 127

#define XNS 6291456   // 3*128^3
#define XCS 2097152   // 128^3
#define XZS 16384     // 128^2
#define OCS 2048383   // 127^3
#define ONS 32774128  // 16*127^3
#define OZS 16129     // 127^2
#define OYS 127

typedef unsigned long long ull;

// Folded weights as (oc even, oc odd) f32x2 pairs: [pair(8)][tap(24)]
// tap = ((ic*2+kd)*2+kh)*2+kw = ickd*4 + kh*2 + kw
__device__ __align__(16) float g_w[8 * 24 * 2];
__device__ __align__(16) float g_b[16];

// Same data in constant memory (copied g_w -> c_w per launch, D2D memcpy node).
// Weight reads then use the constant port: ZERO L1 wavefronts.
__constant__ __align__(16) ull c_w[8 * 24];
__constant__ __align__(16) ull c_b[8];

__global__ void fold_weights_kernel(const float* __restrict__ cw,
                                    const float* __restrict__ cb,
                                    const float* __restrict__ eb) {
    int i = blockIdx.x * blockDim.x + threadIdx.x;
    if (i < 384) {
        int oc = i / 24, tap = i % 24;
        int ic = tap >> 3;
        int kd = (tap >> 2) & 1, kh = (tap >> 1) & 1, kw = tap & 1;
        float s = 0.f;
        int plo = kd ? 0 : 1, phi = kd ? 0 : 2;
        int qlo = kh ? 0 : 1, qhi = kh ? 0 : 2;
        int rlo = kw ? 0 : 1, rhi = kw ? 0 : 2;
        for (int p = plo; p <= phi; ++p)
            for (int q = qlo; q <= qhi; ++q)
                for (int r = rlo; r <= rhi; ++r)
                    s += cw[ic * 432 + oc * 27 + p * 9 + q * 3 + r];
        g_w[(oc >> 1) * 48 + tap * 2 + (oc & 1)] = s * 0.0625f;
    } else if (i < 400) {
        int oc = i - 384;
        g_b[oc] = cb[oc] * 0.5f + eb[oc];
    }
}

// ---- packed fp32x2 helpers (Blackwell FFMA2; ptxas won't emit from C++)
__device__ __forceinline__ void ffma2(ull& d, ull a, ull b) {
    asm("fma.rn.f32x2 %0, %1, %2, %0;" : "+l"(d) : "l"(a), "l"(b));
}
__device__ __forceinline__ ull rep2(float v) {
    ull r; unsigned u = __float_as_uint(v);
    asm("mov.b64 %0, {%1, %1};" : "=l"(r) : "r"(u));
    return r;
}
__device__ __forceinline__ float lo2(ull a) { return __uint_as_float((unsigned)a); }
__device__ __forceinline__ float hi2(ull a) { return __uint_as_float((unsigned)(a >> 32)); }

// One kh-contribution: 4 oc-pairs x (2 w, 2 kw) = 16 FFMA2.
// acc[w'][p]; w'=0 taps (X0,X1), w'=1 taps (X1,X2). w = (kw0, kw1) per pair.
__device__ __forceinline__ void contrib(ull (&acc)[2][4],
                                        ull X0, ull X1, ull X2,
                                        const ulonglong2 (&w)[4]) {
#pragma unroll
    for (int p = 0; p < 4; ++p) {
        ffma2(acc[0][p], X0, w[p].x); ffma2(acc[0][p], X1, w[p].y);
        ffma2(acc[1][p], X1, w[p].x); ffma2(acc[1][p], X2, w[p].y);
    }
}

// Block: 128 threads = 32 lanes x 2 w-segs x 2 oc-octets.
// Thread: w in {w0, w0+1} (w0 = 64*seg + 2*lane), oc in [8*og, 8*og+8), 2 h-rows.
// Grid: (16 h-tiles, 127 d, 4 n)
__global__ void __launch_bounds__(128, 6)
conv2x2x2_kernel(const float* __restrict__ x, float* __restrict__ out) {
    __shared__ __align__(16) float tile[IC][2][9][DIN];   // 27648 B

    const int tid  = threadIdx.x;
    const int lane = tid & 31;
    const int warp = tid >> 5;
    const int og   = warp & 1;      // oc octet
    const int seg  = warp >> 1;     // w segment (0: w<64, 1: w>=64)
    const int ht = blockIdx.x;
    const int d  = blockIdx.y;
    const int n  = blockIdx.z;
    const int h0 = ht * 8;

    // ---- load x tile: 3 ic x 2 d-planes x 9 h rows x 128 w
    {
        const float* xb = x + (size_t)n * XNS + (size_t)d * XZS;
        for (int i = tid; i < 54 * 32; i += 128) {
            int row = i >> 5;
            int col = (i & 31) << 2;
            int ic  = row / 18;
            int rem = row - ic * 18;
            int dz  = rem / 9;
            int hy  = rem - dz * 9;
            int gy  = h0 + hy;
            if (gy > 127) gy = 127;   // clamp (last tile); rows unused by stores
            const float4 v = *(const float4*)(xb + (size_t)ic * XCS +
                                              (size_t)dz * XZS + gy * DIN + col);
            *(float4*)&tile[ic][dz][hy][col] = v;
        }
    }

    const ull FB[4] = { c_b[4 * og], c_b[4 * og + 1],
                        c_b[4 * og + 2], c_b[4 * og + 3] };

    __syncthreads();

    const int w0 = seg * 64 + 2 * lane;
    const bool seg0edge = (seg == 0) && (lane == 31);  // needs x[64] patch
    const bool wlast    = (seg == 1) && (lane == 31);  // w0 = 126 (w=127 invalid)
    float* obase = out + (size_t)n * ONS + (size_t)(8 * og) * OCS +
                   (size_t)d * OZS + w0;

#pragma unroll 1
    for (int hl = 0; hl < 8; hl += 2) {
        const int h = h0 + hl;
        if (h >= DOUT) break;      // uniform across block

        ull A[2][4], B[2][4];      // [w'][oc-pair] for rows h, h+1
#pragma unroll
        for (int p = 0; p < 4; ++p) {
            A[0][p] = FB[p]; A[1][p] = FB[p];
            B[0][p] = FB[p]; B[1][p] = FB[p];
        }

#pragma unroll 1
        for (int ickd = 0; ickd < 6; ++ickd) {
            const int ic = ickd >> 1, kd = ickd & 1;

            // weights via constant port (no L1 traffic)
            ulonglong2 wk0[4], wk1[4];   // kh=0 / kh=1, each (kw0, kw1)
#pragma unroll
            for (int p = 0; p < 4; ++p) {
                const ull* cp = &c_w[(4 * og + p) * 24 + ickd * 4];
                wk0[p] = *(const ulonglong2*)(cp);
                wk1[p] = *(const ulonglong2*)(cp + 2);
            }

#pragma unroll
            for (int r = 0; r < 3; ++r) {
                const float* rp = &tile[ic][kd][hl + r][0];
                const float2 x01 = *(const float2*)(rp + w0);   // dense LDS.64
                float xx2 = __shfl_down_sync(0xffffffffu, x01.x, 1); // x[w0+2]
                if (seg0edge) xx2 = rp[64];   // cross-segment patch
                // (seg1 lane31's xx2 is garbage; feeds only discarded w=127)
                const ull X0 = rep2(x01.x), X1 = rep2(x01.y), X2 = rep2(xx2);

                if (r < 2)  contrib((r == 0) ? A : B, X0, X1, X2, wk0); // kh=0
                if (r >= 1) contrib((r == 1) ? A : B, X0, X1, X2, wk1); // kh=1
            }
        }

        // ---- stores: 8 oc x 2 rows. Dense STG.64 when row base parity even,
        // 2x STG.32 when odd. par(oc=8og+j, row h') = (j + d + h') & 1.
#pragma unroll
        for (int j = 0; j < 8; ++j) {
            const int p = j >> 1, hi = j & 1;
            float* o = obase + (size_t)j * OCS + (size_t)h * OYS;
            {
                const float v0 = hi ? hi2(A[0][p]) : lo2(A[0][p]);
                const float v1 = hi ? hi2(A[1][p]) : lo2(A[1][p]);
                if (((j + d + h) & 1) == 0) {
                    if (!wlast) *(float2*)o = make_float2(v0, v1);
                    else        o[0] = v0;
                } else {
                    o[0] = v0;
                    if (!wlast) o[1] = v1;
                }
            }
            if (h + 1 < DOUT) {
                float* q = o + OYS;
                const float v0 = hi ? hi2(B[0][p]) : lo2(B[0][p]);
                const float v1 = hi ? hi2(B[1][p]) : lo2(B[1][p]);
                if (((j + d + h + 1) & 1) == 0) {
                    if (!wlast) *(float2*)q = make_float2(v0, v1);
                    else        q[0] = v0;
                } else {
                    q[0] = v0;
                    if (!wlast) q[1] = v1;
                }
            }
        }
    }
}

extern "C" void kernel_launch(void* const* d_in, const int* in_sizes, int n_in,
                              void* d_out, int out_size) {
    const float* x  = (const float*)d_in[0];
    const float* cw = (const float*)d_in[1];
    const float* cb = (const float*)d_in[2];
    const float* eb = (const float*)d_in[3];
    float* out = (float*)d_out;

    fold_weights_kernel<<<1, 512>>>(cw, cb, eb);

    // Publish folded weights to constant memory (D2D memcpy, capturable).
    void *gw = nullptr, *gb = nullptr;
    cudaGetSymbolAddress(&gw, g_w);
    cudaGetSymbolAddress(&gb, g_b);
    cudaMemcpyToSymbolAsync(c_w, gw, sizeof(c_w), 0, cudaMemcpyDeviceToDevice, 0);
    cudaMemcpyToSymbolAsync(c_b, gb, sizeof(c_b), 0, cudaMemcpyDeviceToDevice, 0);

    dim3 grid(16, DOUT, 4);   // h-tiles, d, n
    conv2x2x2_kernel<<<grid, 128>>>(x, out);
}